// round 15
// baseline (speedup 1.0000x reference)
#include <cuda_runtime.h>

#define BATCH 2048
#define IN_SZ 40960
#define HID 256
#define NT 1024                      // threads per CTA
#define ROW_F4 (IN_SZ / 4)           // 10240 uint4 per one-hot row
#define ROW_ITERS (ROW_F4 / NT)      // 10 uint4-groups per thread per perspective

__device__ float g_ftw_t[(size_t)IN_SZ * HID];   // 41.9 MB transposed weights

// ---------------------------------------------------------------------------
// Kernel 1: transpose ft_w [256, 40960] -> g_ftw_t [40960, 256]
// ---------------------------------------------------------------------------
__global__ __launch_bounds__(256) void transpose_ft(const float* __restrict__ ft_w) {
    __shared__ float tile[32][33];
    int x = blockIdx.x * 32 + threadIdx.x;
    int y = blockIdx.y * 32 + threadIdx.y;
#pragma unroll
    for (int k = 0; k < 32; k += 8)
        tile[threadIdx.y + k][threadIdx.x] = ft_w[(size_t)(y + k) * IN_SZ + x];
    __syncthreads();
    int ox = blockIdx.y * 32 + threadIdx.x;
    int oy = blockIdx.x * 32 + threadIdx.y;
#pragma unroll
    for (int k = 0; k < 32; k += 8)
        g_ftw_t[(size_t)(oy + k) * HID + ox] = tile[threadIdx.x][threadIdx.y + k];
}

// ---------------------------------------------------------------------------
// Kernel 2: one CTA (1024 threads) per row; 2 CTAs/SM, 6.9 waves.
//   Wider CTA quarters the tail vs R11; deep wave count desynchronizes
//   co-resident CTAs so a tailing CTA is covered by its streaming neighbor.
// ---------------------------------------------------------------------------
__global__ __launch_bounds__(NT, 2) void nnue_fused(
    const float* __restrict__ white, const float* __restrict__ black,
    const float* __restrict__ stm,
    const float* __restrict__ ft_b,
    const float* __restrict__ l1w, const float* __restrict__ l1b,
    const float* __restrict__ l2w, const float* __restrict__ l2b,
    const float* __restrict__ l3w, const float* __restrict__ l3b,
    float* __restrict__ out)
{
    const int b   = blockIdx.x;
    const int tid = threadIdx.x;

    __shared__ int    cnt[2];
    __shared__ int    idx[2][32];
    __shared__ float4 red[2][16][64];  // [persp][fgroup][col]  32 KB
    __shared__ float  hid[2 * HID];
    __shared__ float  x1s[32];
    __shared__ float  x2s[32];

    if (tid < 2) cnt[tid] = 0;
    __syncthreads();

    const int c  = tid & 63;
    const int fg = tid >> 6;           // 0..15
    const float4* __restrict__ ftw4 = reinterpret_cast<const float4*>(g_ftw_t);

    // ---- Phase A: scan white, batch-2 streaming loads ----
    {
        const uint4* src = reinterpret_cast<const uint4*>(white) + (size_t)b * ROW_F4;
        for (int it = 0; it < ROW_ITERS; it += 2) {
            uint4 f[2];
#pragma unroll
            for (int u = 0; u < 2; ++u)
                f[u] = __ldcs(&src[(it + u) * NT + tid]);
#pragma unroll
            for (int u = 0; u < 2; ++u) {
                if (f[u].x | f[u].y | f[u].z | f[u].w) {
                    int base = ((it + u) * NT + tid) * 4;
                    if (f[u].x) { int s = atomicAdd(&cnt[0], 1); idx[0][s] = base + 0; }
                    if (f[u].y) { int s = atomicAdd(&cnt[0], 1); idx[0][s] = base + 1; }
                    if (f[u].z) { int s = atomicAdd(&cnt[0], 1); idx[0][s] = base + 2; }
                    if (f[u].w) { int s = atomicAdd(&cnt[0], 1); idx[0][s] = base + 3; }
                }
            }
        }
    }
    __syncthreads();
    const int wc = cnt[0];

    // ---- Phase B: scan black, white gather interleaved ----
    float4 aw = make_float4(0.f, 0.f, 0.f, 0.f);
    float4 ab = make_float4(0.f, 0.f, 0.f, 0.f);
    {
        const uint4* src = reinterpret_cast<const uint4*>(black) + (size_t)b * ROW_F4;
        int g = 0;
        for (int it = 0; it < ROW_ITERS; it += 2) {
            uint4 f[2];
#pragma unroll
            for (int u = 0; u < 2; ++u)
                f[u] = __ldcs(&src[(it + u) * NT + tid]);
            // one white-gather step per iteration (2 steps cover wc <= 32)
            if (g < 2) {
                int k = fg + 16 * g;
                if (k < wc) {
                    float4 v = ftw4[(size_t)idx[0][k] * 64 + c];
                    aw.x += v.x; aw.y += v.y; aw.z += v.z; aw.w += v.w;
                }
            }
            ++g;
#pragma unroll
            for (int u = 0; u < 2; ++u) {
                if (f[u].x | f[u].y | f[u].z | f[u].w) {
                    int base = ((it + u) * NT + tid) * 4;
                    if (f[u].x) { int s = atomicAdd(&cnt[1], 1); idx[1][s] = base + 0; }
                    if (f[u].y) { int s = atomicAdd(&cnt[1], 1); idx[1][s] = base + 1; }
                    if (f[u].z) { int s = atomicAdd(&cnt[1], 1); idx[1][s] = base + 2; }
                    if (f[u].w) { int s = atomicAdd(&cnt[1], 1); idx[1][s] = base + 3; }
                }
            }
        }
    }
    __syncthreads();
    const int bc = cnt[1];

    // ---- Tail: black gather (16-way feature parallelism, chain <= 2) ----
#pragma unroll 2
    for (int j = fg; j < bc; j += 16) {
        float4 v = ftw4[(size_t)idx[1][j] * 64 + c];
        ab.x += v.x; ab.y += v.y; ab.z += v.z; ab.w += v.w;
    }
    red[0][fg][c] = aw;
    red[1][fg][c] = ab;
    __syncthreads();

    const bool s = (stm[b] != 0.f);

    if (tid < 128) {
        int p  = tid >> 6;
        int cc = tid & 63;
        float4 bi = reinterpret_cast<const float4*>(ft_b)[cc];
        float4 t0 = red[p][0][cc];
#pragma unroll
        for (int q = 1; q < 16; ++q) {
            float4 v = red[p][q][cc];
            t0.x += v.x; t0.y += v.y; t0.z += v.z; t0.w += v.w;
        }
        float4 r;
        r.x = fminf(fmaxf(t0.x + bi.x, 0.f), 1.f);
        r.y = fminf(fmaxf(t0.y + bi.y, 0.f), 1.f);
        r.z = fminf(fmaxf(t0.z + bi.z, 0.f), 1.f);
        r.w = fminf(fmaxf(t0.w + bi.w, 0.f), 1.f);
        int half = ((p == 0) == s) ? 0 : 1;
        reinterpret_cast<float4*>(hid)[half * 64 + cc] = r;
    }
    __syncthreads();

    // ---- MLP ----
    // Layer 1: 512 -> 32, one warp per output (full-warp reduce)
    {
        int k    = tid >> 5;           // output 0..31
        int lane = tid & 31;
        const float* w = l1w + k * 512;
        float p = 0.f;
#pragma unroll
        for (int j = lane; j < 512; j += 32) p += hid[j] * w[j];
        p += __shfl_down_sync(0xffffffffu, p, 16);
        p += __shfl_down_sync(0xffffffffu, p, 8);
        p += __shfl_down_sync(0xffffffffu, p, 4);
        p += __shfl_down_sync(0xffffffffu, p, 2);
        p += __shfl_down_sync(0xffffffffu, p, 1);
        if (lane == 0) x1s[k] = fminf(fmaxf(p + l1b[k], 0.f), 1.f);
    }
    __syncthreads();

    // Layer 2: 32 -> 32
    if (tid < 32) {
        float p = l2b[tid];
        const float* w = l2w + tid * 32;
#pragma unroll
        for (int j = 0; j < 32; ++j) p += x1s[j] * w[j];
        x2s[tid] = fminf(fmaxf(p, 0.f), 1.f);
    }
    __syncwarp(0xffffffffu);

    // Layer 3: 32 -> 1
    if (tid < 32) {
        float p = x2s[tid] * l3w[tid];
        p += __shfl_down_sync(0xffffffffu, p, 16);
        p += __shfl_down_sync(0xffffffffu, p, 8);
        p += __shfl_down_sync(0xffffffffu, p, 4);
        p += __shfl_down_sync(0xffffffffu, p, 2);
        p += __shfl_down_sync(0xffffffffu, p, 1);
        if (tid == 0) out[b] = p + l3b[0];
    }
}

// ---------------------------------------------------------------------------
// Launch
// ---------------------------------------------------------------------------
extern "C" void kernel_launch(void* const* d_in, const int* in_sizes, int n_in,
                              void* d_out, int out_size) {
    const float* white = (const float*)d_in[0];
    const float* black = (const float*)d_in[1];
    const float* stm   = (const float*)d_in[2];
    const float* ft_w  = (const float*)d_in[3];
    const float* ft_b  = (const float*)d_in[4];
    const float* l1w   = (const float*)d_in[5];
    const float* l1b   = (const float*)d_in[6];
    const float* l2w   = (const float*)d_in[7];
    const float* l2b   = (const float*)d_in[8];
    const float* l3w   = (const float*)d_in[9];
    const float* l3b   = (const float*)d_in[10];
    float* out = (float*)d_out;

    dim3 tb(32, 8);
    dim3 tg(IN_SZ / 32, HID / 32);
    transpose_ft<<<tg, tb>>>(ft_w);

    nnue_fused<<<BATCH, NT>>>(white, black, stm, ft_b,
                              l1w, l1b, l2w, l2b, l3w, l3b, out);
}

// round 16
// speedup vs baseline: 1.0198x; 1.0198x over previous
#include <cuda_runtime.h>

#define BATCH 2048
#define IN_SZ 40960
#define HID 256
#define NT 1024                      // threads per CTA
#define ROW_F4 (IN_SZ / 4)           // 10240 uint4 per one-hot row
#define ROW_ITERS (ROW_F4 / NT)      // 10 uint4-groups per thread per perspective

__device__ float g_ftw_t[(size_t)IN_SZ * HID];   // 41.9 MB transposed weights

// ---------------------------------------------------------------------------
// Kernel 1: transpose ft_w [256, 40960] -> g_ftw_t [40960, 256]
// ---------------------------------------------------------------------------
__global__ __launch_bounds__(256) void transpose_ft(const float* __restrict__ ft_w) {
    __shared__ float tile[32][33];
    int x = blockIdx.x * 32 + threadIdx.x;
    int y = blockIdx.y * 32 + threadIdx.y;
#pragma unroll
    for (int k = 0; k < 32; k += 8)
        tile[threadIdx.y + k][threadIdx.x] = ft_w[(size_t)(y + k) * IN_SZ + x];
    __syncthreads();
    int ox = blockIdx.y * 32 + threadIdx.x;
    int oy = blockIdx.x * 32 + threadIdx.y;
#pragma unroll
    for (int k = 0; k < 32; k += 8)
        g_ftw_t[(size_t)(oy + k) * HID + ox] = tile[threadIdx.x][threadIdx.y + k];
}

// ---------------------------------------------------------------------------
// Scan helper: batch-N streaming chunk with index push (macro keeps regs flat)
// ---------------------------------------------------------------------------
__device__ __forceinline__ void scan_chunk4(const uint4* __restrict__ src, int it0,
                                            int tid, int* cnt, int* idxp) {
    uint4 f[4];
#pragma unroll
    for (int u = 0; u < 4; ++u) f[u] = __ldcs(&src[(it0 + u) * NT + tid]);
#pragma unroll
    for (int u = 0; u < 4; ++u) {
        if (f[u].x | f[u].y | f[u].z | f[u].w) {
            int base = ((it0 + u) * NT + tid) * 4;
            if (f[u].x) { int s = atomicAdd(cnt, 1); idxp[s] = base + 0; }
            if (f[u].y) { int s = atomicAdd(cnt, 1); idxp[s] = base + 1; }
            if (f[u].z) { int s = atomicAdd(cnt, 1); idxp[s] = base + 2; }
            if (f[u].w) { int s = atomicAdd(cnt, 1); idxp[s] = base + 3; }
        }
    }
}

__device__ __forceinline__ void scan_chunk2(const uint4* __restrict__ src, int it0,
                                            int tid, int* cnt, int* idxp) {
    uint4 f[2];
#pragma unroll
    for (int u = 0; u < 2; ++u) f[u] = __ldcs(&src[(it0 + u) * NT + tid]);
#pragma unroll
    for (int u = 0; u < 2; ++u) {
        if (f[u].x | f[u].y | f[u].z | f[u].w) {
            int base = ((it0 + u) * NT + tid) * 4;
            if (f[u].x) { int s = atomicAdd(cnt, 1); idxp[s] = base + 0; }
            if (f[u].y) { int s = atomicAdd(cnt, 1); idxp[s] = base + 1; }
            if (f[u].z) { int s = atomicAdd(cnt, 1); idxp[s] = base + 2; }
            if (f[u].w) { int s = atomicAdd(cnt, 1); idxp[s] = base + 3; }
        }
    }
}

// ---------------------------------------------------------------------------
// Kernel 2: one CTA (1024 threads) per row; 2 CTAs/SM, ~6.9 wave slots.
// batch-4 streaming (R14's proven depth) + halved drain + 16-way tail.
// ---------------------------------------------------------------------------
__global__ __launch_bounds__(NT, 2) void nnue_fused(
    const float* __restrict__ white, const float* __restrict__ black,
    const float* __restrict__ stm,
    const float* __restrict__ ft_b,
    const float* __restrict__ l1w, const float* __restrict__ l1b,
    const float* __restrict__ l2w, const float* __restrict__ l2b,
    const float* __restrict__ l3w, const float* __restrict__ l3b,
    float* __restrict__ out)
{
    const int b   = blockIdx.x;
    const int tid = threadIdx.x;

    __shared__ int    cnt[2];
    __shared__ int    idx[2][32];
    __shared__ float4 red[2][16][64];  // 32 KB
    __shared__ float  hid[2 * HID];
    __shared__ float  x1s[32];
    __shared__ float  x2s[32];

    if (tid < 2) cnt[tid] = 0;
    __syncthreads();

    const int c  = tid & 63;
    const int fg = tid >> 6;           // 0..15
    const float4* __restrict__ ftw4 = reinterpret_cast<const float4*>(g_ftw_t);

    // ---- Phase A: scan white (10 iters = 4+4+2, batch-4 depth) ----
    {
        const uint4* src = reinterpret_cast<const uint4*>(white) + (size_t)b * ROW_F4;
        scan_chunk4(src, 0, tid, &cnt[0], idx[0]);
        scan_chunk4(src, 4, tid, &cnt[0], idx[0]);
        scan_chunk2(src, 8, tid, &cnt[0], idx[0]);
    }
    __syncthreads();
    const int wc = cnt[0];

    // ---- Phase B: scan black, white gather interleaved ----
    float4 aw = make_float4(0.f, 0.f, 0.f, 0.f);
    float4 ab = make_float4(0.f, 0.f, 0.f, 0.f);
    {
        const uint4* src = reinterpret_cast<const uint4*>(black) + (size_t)b * ROW_F4;
        scan_chunk4(src, 0, tid, &cnt[1], idx[1]);
        // white gather step 0 (16-way): k = fg
        if (fg < wc) {
            float4 v = ftw4[(size_t)idx[0][fg] * 64 + c];
            aw.x += v.x; aw.y += v.y; aw.z += v.z; aw.w += v.w;
        }
        scan_chunk4(src, 4, tid, &cnt[1], idx[1]);
        // white gather step 1: k = fg + 16
        if (fg + 16 < wc) {
            float4 v = ftw4[(size_t)idx[0][fg + 16] * 64 + c];
            aw.x += v.x; aw.y += v.y; aw.z += v.z; aw.w += v.w;
        }
        scan_chunk2(src, 8, tid, &cnt[1], idx[1]);
    }
    __syncthreads();
    const int bc = cnt[1];

    // ---- Tail: black gather (16-way, chain <= 2) ----
#pragma unroll 2
    for (int j = fg; j < bc; j += 16) {
        float4 v = ftw4[(size_t)idx[1][j] * 64 + c];
        ab.x += v.x; ab.y += v.y; ab.z += v.z; ab.w += v.w;
    }
    red[0][fg][c] = aw;
    red[1][fg][c] = ab;
    __syncthreads();

    const bool s = (stm[b] != 0.f);

    if (tid < 128) {
        int p  = tid >> 6;
        int cc = tid & 63;
        float4 bi = reinterpret_cast<const float4*>(ft_b)[cc];
        float4 t0 = red[p][0][cc];
#pragma unroll
        for (int q = 1; q < 16; ++q) {
            float4 v = red[p][q][cc];
            t0.x += v.x; t0.y += v.y; t0.z += v.z; t0.w += v.w;
        }
        float4 r;
        r.x = fminf(fmaxf(t0.x + bi.x, 0.f), 1.f);
        r.y = fminf(fmaxf(t0.y + bi.y, 0.f), 1.f);
        r.z = fminf(fmaxf(t0.z + bi.z, 0.f), 1.f);
        r.w = fminf(fmaxf(t0.w + bi.w, 0.f), 1.f);
        int half = ((p == 0) == s) ? 0 : 1;
        reinterpret_cast<float4*>(hid)[half * 64 + cc] = r;
    }
    __syncthreads();

    // ---- MLP ----
    // Layer 1: 512 -> 32, one warp per output
    {
        int k    = tid >> 5;           // output 0..31
        int lane = tid & 31;
        const float* w = l1w + k * 512;
        float p = 0.f;
#pragma unroll
        for (int j = lane; j < 512; j += 32) p += hid[j] * w[j];
        p += __shfl_down_sync(0xffffffffu, p, 16);
        p += __shfl_down_sync(0xffffffffu, p, 8);
        p += __shfl_down_sync(0xffffffffu, p, 4);
        p += __shfl_down_sync(0xffffffffu, p, 2);
        p += __shfl_down_sync(0xffffffffu, p, 1);
        if (lane == 0) x1s[k] = fminf(fmaxf(p + l1b[k], 0.f), 1.f);
    }
    __syncthreads();

    // Layer 2: 32 -> 32
    if (tid < 32) {
        float p = l2b[tid];
        const float* w = l2w + tid * 32;
#pragma unroll
        for (int j = 0; j < 32; ++j) p += x1s[j] * w[j];
        x2s[tid] = fminf(fmaxf(p, 0.f), 1.f);
    }
    __syncwarp(0xffffffffu);

    // Layer 3: 32 -> 1
    if (tid < 32) {
        float p = x2s[tid] * l3w[tid];
        p += __shfl_down_sync(0xffffffffu, p, 16);
        p += __shfl_down_sync(0xffffffffu, p, 8);
        p += __shfl_down_sync(0xffffffffu, p, 4);
        p += __shfl_down_sync(0xffffffffu, p, 2);
        p += __shfl_down_sync(0xffffffffu, p, 1);
        if (tid == 0) out[b] = p + l3b[0];
    }
}

// ---------------------------------------------------------------------------
// Launch
// ---------------------------------------------------------------------------
extern "C" void kernel_launch(void* const* d_in, const int* in_sizes, int n_in,
                              void* d_out, int out_size) {
    const float* white = (const float*)d_in[0];
    const float* black = (const float*)d_in[1];
    const float* stm   = (const float*)d_in[2];
    const float* ft_w  = (const float*)d_in[3];
    const float* ft_b  = (const float*)d_in[4];
    const float* l1w   = (const float*)d_in[5];
    const float* l1b   = (const float*)d_in[6];
    const float* l2w   = (const float*)d_in[7];
    const float* l2b   = (const float*)d_in[8];
    const float* l3w   = (const float*)d_in[9];
    const float* l3b   = (const float*)d_in[10];
    float* out = (float*)d_out;

    dim3 tb(32, 8);
    dim3 tg(IN_SZ / 32, HID / 32);
    transpose_ft<<<tg, tb>>>(ft_w);

    nnue_fused<<<BATCH, NT>>>(white, black, stm, ft_b,
                              l1w, l1b, l2w, l2b, l3w, l3b, out);
}

// round 17
// speedup vs baseline: 1.1031x; 1.0817x over previous
#include <cuda_runtime.h>

#define BATCH 2048
#define IN_SZ 40960
#define HID 256
#define NT 512
#define ROW_F4 (IN_SZ / 4)           // 10240 uint4 per perspective-row
#define P_ITERS (ROW_F4 / NT)        // 20 iterations per perspective CTA

__device__ float g_ftw_t[(size_t)IN_SZ * HID];     // 41.9 MB transposed weights
__device__ float g_hid[(size_t)BATCH * 2 * HID];   // 4 MB ordered hidden halves
__device__ int   g_flag[BATCH];                    // zero-init; self-reset each run

// ---------------------------------------------------------------------------
// Kernel 1: transpose ft_w [256, 40960] -> g_ftw_t [40960, 256]
// ---------------------------------------------------------------------------
__global__ __launch_bounds__(256) void transpose_ft(const float* __restrict__ ft_w) {
    __shared__ float tile[32][33];
    int x = blockIdx.x * 32 + threadIdx.x;
    int y = blockIdx.y * 32 + threadIdx.y;
#pragma unroll
    for (int k = 0; k < 32; k += 8)
        tile[threadIdx.y + k][threadIdx.x] = ft_w[(size_t)(y + k) * IN_SZ + x];
    __syncthreads();
    int ox = blockIdx.y * 32 + threadIdx.x;
    int oy = blockIdx.x * 32 + threadIdx.y;
#pragma unroll
    for (int k = 0; k < 32; k += 8)
        g_ftw_t[(size_t)(oy + k) * HID + ox] = tile[threadIdx.x][threadIdx.y + k];
}

// ---------------------------------------------------------------------------
// Kernel 2: one CTA per (row, perspective). 4096 CTAs, 512 threads, 4/SM,
// 6.9 waves. Second finisher of each row pair runs the fused MLP.
// ---------------------------------------------------------------------------
__global__ __launch_bounds__(NT, 4) void nnue_half(
    const float* __restrict__ white, const float* __restrict__ black,
    const float* __restrict__ stm,
    const float* __restrict__ ft_b,
    const float* __restrict__ l1w, const float* __restrict__ l1b,
    const float* __restrict__ l2w, const float* __restrict__ l2b,
    const float* __restrict__ l3w, const float* __restrict__ l3b,
    float* __restrict__ out)
{
    const int b   = blockIdx.x >> 1;
    const int p   = blockIdx.x & 1;      // 0 = white, 1 = black
    const int tid = threadIdx.x;

    __shared__ int    cnt;
    __shared__ int    idx[32];
    __shared__ int    role;              // second finisher?
    __shared__ float4 red[8][64];        // 8 KB
    __shared__ float  hid[2 * HID];      // MLP input (both halves)
    __shared__ float  x1s[32];
    __shared__ float  x2s[32];

    if (tid == 0) cnt = 0;
    __syncthreads();

    // ---- scan own perspective half-row (batch-4 streaming) ----
    {
        const uint4* src = reinterpret_cast<const uint4*>(p ? black : white)
                         + (size_t)b * ROW_F4;
        for (int it = 0; it < P_ITERS; it += 4) {
            uint4 f[4];
#pragma unroll
            for (int u = 0; u < 4; ++u)
                f[u] = __ldcs(&src[(it + u) * NT + tid]);
#pragma unroll
            for (int u = 0; u < 4; ++u) {
                if (f[u].x | f[u].y | f[u].z | f[u].w) {
                    int base = ((it + u) * NT + tid) * 4;
                    if (f[u].x) { int s = atomicAdd(&cnt, 1); idx[s] = base + 0; }
                    if (f[u].y) { int s = atomicAdd(&cnt, 1); idx[s] = base + 1; }
                    if (f[u].z) { int s = atomicAdd(&cnt, 1); idx[s] = base + 2; }
                    if (f[u].w) { int s = atomicAdd(&cnt, 1); idx[s] = base + 3; }
                }
            }
        }
    }
    __syncthreads();
    const int nf = cnt;

    // ---- gather own perspective (8-way feature groups) ----
    const int c  = tid & 63;
    const int fg = tid >> 6;             // 0..7
    const float4* __restrict__ ftw4 = reinterpret_cast<const float4*>(g_ftw_t);

    float4 acc = make_float4(0.f, 0.f, 0.f, 0.f);
#pragma unroll 4
    for (int j = fg; j < nf; j += 8) {
        float4 v = ftw4[(size_t)idx[j] * 64 + c];
        acc.x += v.x; acc.y += v.y; acc.z += v.z; acc.w += v.w;
    }
    red[fg][c] = acc;
    __syncthreads();

    // ---- reduce + bias + clip + ordered store of this half to g_hid ----
    const bool s = (stm[b] != 0.f);
    const int half = ((p == 0) == s) ? 0 : 1;   // stm: white first else black first
    if (tid < 64) {
        float4 bi = reinterpret_cast<const float4*>(ft_b)[tid];
        float4 t0 = red[0][tid];
#pragma unroll
        for (int q = 1; q < 8; ++q) {
            float4 v = red[q][tid];
            t0.x += v.x; t0.y += v.y; t0.z += v.z; t0.w += v.w;
        }
        float4 r;
        r.x = fminf(fmaxf(t0.x + bi.x, 0.f), 1.f);
        r.y = fminf(fmaxf(t0.y + bi.y, 0.f), 1.f);
        r.z = fminf(fmaxf(t0.z + bi.z, 0.f), 1.f);
        r.w = fminf(fmaxf(t0.w + bi.w, 0.f), 1.f);
        reinterpret_cast<float4*>(g_hid)[(size_t)b * 128 + half * 64 + tid] = r;
    }
    __syncthreads();

    // ---- pair handshake: second finisher runs the MLP ----
    if (tid == 0) {
        __threadfence();                          // release own hid half
        int old = atomicAdd(&g_flag[b], 1);
        if (old == 1) __threadfence();            // acquire partner's half
        role = old;
    }
    __syncthreads();
    if (role != 1) return;                        // first finisher exits

    // load both ordered halves (own half L2-hot; partner's too)
    {
        float4 v = reinterpret_cast<const float4*>(g_hid)[(size_t)b * 128 + (tid & 127)];
        if (tid < 128) reinterpret_cast<float4*>(hid)[tid] = v;
    }
    if (tid == 0) g_flag[b] = 0;                  // reset for next graph replay
    __syncthreads();

    // ---- MLP ----
    // Layer 1: 512 -> 32, 16 threads per output
    {
        int k   = tid >> 4;
        int s16 = tid & 15;
        const float* w = l1w + k * 512;
        float q = 0.f;
#pragma unroll
        for (int j = s16; j < 512; j += 16) q += hid[j] * w[j];
        q += __shfl_down_sync(0xffffffffu, q, 8, 16);
        q += __shfl_down_sync(0xffffffffu, q, 4, 16);
        q += __shfl_down_sync(0xffffffffu, q, 2, 16);
        q += __shfl_down_sync(0xffffffffu, q, 1, 16);
        if (s16 == 0) x1s[k] = fminf(fmaxf(q + l1b[k], 0.f), 1.f);
    }
    __syncthreads();

    // Layer 2: 32 -> 32
    if (tid < 32) {
        float q = l2b[tid];
        const float* w = l2w + tid * 32;
#pragma unroll
        for (int j = 0; j < 32; ++j) q += x1s[j] * w[j];
        x2s[tid] = fminf(fmaxf(q, 0.f), 1.f);
    }
    __syncwarp(0xffffffffu);

    // Layer 3: 32 -> 1
    if (tid < 32) {
        float q = x2s[tid] * l3w[tid];
        q += __shfl_down_sync(0xffffffffu, q, 16);
        q += __shfl_down_sync(0xffffffffu, q, 8);
        q += __shfl_down_sync(0xffffffffu, q, 4);
        q += __shfl_down_sync(0xffffffffu, q, 2);
        q += __shfl_down_sync(0xffffffffu, q, 1);
        if (tid == 0) out[b] = q + l3b[0];
    }
}

// ---------------------------------------------------------------------------
// Launch
// ---------------------------------------------------------------------------
extern "C" void kernel_launch(void* const* d_in, const int* in_sizes, int n_in,
                              void* d_out, int out_size) {
    const float* white = (const float*)d_in[0];
    const float* black = (const float*)d_in[1];
    const float* stm   = (const float*)d_in[2];
    const float* ft_w  = (const float*)d_in[3];
    const float* ft_b  = (const float*)d_in[4];
    const float* l1w   = (const float*)d_in[5];
    const float* l1b   = (const float*)d_in[6];
    const float* l2w   = (const float*)d_in[7];
    const float* l2b   = (const float*)d_in[8];
    const float* l3w   = (const float*)d_in[9];
    const float* l3b   = (const float*)d_in[10];
    float* out = (float*)d_out;

    dim3 tb(32, 8);
    dim3 tg(IN_SZ / 32, HID / 32);
    transpose_ft<<<tg, tb>>>(ft_w);

    nnue_half<<<2 * BATCH, NT>>>(white, black, stm, ft_b,
                                 l1w, l1b, l2w, l2b, l3w, l3b, out);
}